// round 2
// baseline (speedup 1.0000x reference)
#include <cuda_runtime.h>
#include <math.h>

#define NN   100000
#define EE   1600000
#define INC  128
#define HID  64
#define NCLS 40

#define SCAN_B 512
#define NB_SCAN ((NN + SCAN_B - 1) / SCAN_B)   // 196

// ---------------- device scratch (no allocations allowed) ----------------
__device__ int   g_is64;
__device__ int   g_deg[NN];
__device__ float g_dis[NN];
__device__ int   g_off[NN + 1];
__device__ int   g_pos[NN];
__device__ int   g_srcs[EE];
__device__ float g_h[(size_t)NN * HID];    // dis-scaled x@W1
__device__ float g_h2[(size_t)NN * HID];   // relu(agg1 + b1)
__device__ float g_g[(size_t)NN * NCLS];   // dis-scaled h2@W2
__device__ int   g_bsum[256];
__device__ int   g_bsumx[256];

// ---------------- dtype probe: int32 vs int64 edge_index ----------------
__global__ void k_probe(const int* __restrict__ e32) {
    // int64 little-endian with values < 2^31 -> every odd word is 0.
    // int32 random values in [0,1e5) -> odd words almost surely nonzero.
    int all0 = 1;
    for (int i = 0; i < 64; i++)
        if (e32[2 * i + 1] != 0) { all0 = 0; break; }
    g_is64 = all0;
}

__device__ __forceinline__ int load_idx(const void* eidx, size_t pos, int is64) {
    if (is64) return (int)((const long long*)eidx)[pos];
    return ((const int*)eidx)[pos];
}

// ---------------- CSR build ----------------
__global__ void k_init_deg() {
    int i = blockIdx.x * blockDim.x + threadIdx.x;
    if (i < NN) g_deg[i] = 0;
}

__global__ void k_count(const void* __restrict__ eidx) {
    int e = blockIdx.x * blockDim.x + threadIdx.x;
    if (e >= EE) return;
    int is64 = g_is64;
    int d = load_idx(eidx, (size_t)EE + e, is64);
    if ((unsigned)d < NN) atomicAdd(&g_deg[d], 1);
}

__global__ void k_scan1() {
    __shared__ int s[SCAN_B];
    int tid = threadIdx.x;
    int i = blockIdx.x * SCAN_B + tid;
    int v = (i < NN) ? g_deg[i] : 0;
    s[tid] = v;
    __syncthreads();
    for (int o = 1; o < SCAN_B; o <<= 1) {
        int t = 0;
        if (tid >= o) t = s[tid - o];
        __syncthreads();
        s[tid] += t;
        __syncthreads();
    }
    if (i < NN) g_off[i] = s[tid] - v;      // exclusive within block
    if (tid == SCAN_B - 1) g_bsum[blockIdx.x] = s[tid];
}

__global__ void k_scan2() {
    __shared__ int s[256];
    int tid = threadIdx.x;
    int v = (tid < NB_SCAN) ? g_bsum[tid] : 0;
    s[tid] = v;
    __syncthreads();
    for (int o = 1; o < 256; o <<= 1) {
        int t = 0;
        if (tid >= o) t = s[tid - o];
        __syncthreads();
        s[tid] += t;
        __syncthreads();
    }
    g_bsumx[tid] = s[tid] - v;              // exclusive block offsets
}

__global__ void k_scan3() {
    int i = blockIdx.x * blockDim.x + threadIdx.x;
    if (i < NN) {
        int o = g_off[i] + g_bsumx[i >> 9];
        g_off[i] = o;
        g_pos[i] = o;
        g_dis[i] = rsqrtf((float)(g_deg[i] + 1));  // +1 self loop
    }
    if (i == 0) g_off[NN] = EE;
}

__global__ void k_fill(const void* __restrict__ eidx) {
    int e = blockIdx.x * blockDim.x + threadIdx.x;
    if (e >= EE) return;
    int is64 = g_is64;
    int s = load_idx(eidx, (size_t)e, is64);
    int d = load_idx(eidx, (size_t)EE + e, is64);
    if ((unsigned)d < NN && (unsigned)s < NN) {
        int p = atomicAdd(&g_pos[d], 1);
        if ((unsigned)p < EE) g_srcs[p] = s;
    }
}

// ---------------- GEMM1: g_h = dis * (x @ W1), [N,128]@[128,64] ----------------
__global__ __launch_bounds__(256) void k_gemm1(const float* __restrict__ x,
                                               const float* __restrict__ W1) {
    __shared__ float xs[32][INC];      // 16 KB
    __shared__ float ws[INC * HID];    // 32 KB
    int tid = threadIdx.x;
    int rowBase = blockIdx.x * 32;

    const float4* x4 = (const float4*)(x + (size_t)rowBase * INC);
    float4* xs4 = (float4*)&xs[0][0];
    #pragma unroll
    for (int j = tid; j < 32 * INC / 4; j += 256) xs4[j] = x4[j];
    const float4* w4 = (const float4*)W1;
    float4* ws4 = (float4*)ws;
    #pragma unroll
    for (int j = tid; j < INC * HID / 4; j += 256) ws4[j] = w4[j];
    __syncthreads();

    int ra = tid >> 4;          // 0..15
    int rb = ra + 16;
    int c0 = (tid & 15) * 4;

    float4 acc0 = make_float4(0.f, 0.f, 0.f, 0.f);
    float4 acc1 = make_float4(0.f, 0.f, 0.f, 0.f);
    #pragma unroll 4
    for (int k = 0; k < INC; k++) {
        float a0 = xs[ra][k];
        float a1 = xs[rb][k];
        float4 w = *(const float4*)&ws[k * HID + c0];
        acc0.x += a0 * w.x; acc0.y += a0 * w.y; acc0.z += a0 * w.z; acc0.w += a0 * w.w;
        acc1.x += a1 * w.x; acc1.y += a1 * w.y; acc1.z += a1 * w.z; acc1.w += a1 * w.w;
    }
    float d0 = g_dis[rowBase + ra];
    float d1 = g_dis[rowBase + rb];
    acc0.x *= d0; acc0.y *= d0; acc0.z *= d0; acc0.w *= d0;
    acc1.x *= d1; acc1.y *= d1; acc1.z *= d1; acc1.w *= d1;
    *(float4*)&g_h[(size_t)(rowBase + ra) * HID + c0] = acc0;
    *(float4*)&g_h[(size_t)(rowBase + rb) * HID + c0] = acc1;
}

// ---------------- Agg1: h2 = relu(dis*(self + sum nbr g_h) + b1) ----------------
__global__ __launch_bounds__(256) void k_agg1(const float* __restrict__ b1) {
    int gwarp = (blockIdx.x * blockDim.x + threadIdx.x) >> 5;
    int lane = threadIdx.x & 31;
    if (gwarp >= NN) return;
    int node = gwarp;

    const float2* hb = (const float2*)g_h;
    float2 acc = hb[(size_t)node * 32 + lane];   // self term (already dis-scaled)

    int beg = g_off[node], end = g_off[node + 1];
    for (int e = beg; e < end; ++e) {
        int s = g_srcs[e];
        float2 v = hb[(size_t)s * 32 + lane];
        acc.x += v.x; acc.y += v.y;
    }

    float di = g_dis[node];
    float2 b = *(const float2*)&b1[lane * 2];
    float2 r;
    r.x = fmaxf(di * acc.x + b.x, 0.f);
    r.y = fmaxf(di * acc.y + b.y, 0.f);
    ((float2*)g_h2)[(size_t)node * 32 + lane] = r;
}

// ---------------- GEMM2: g_g = dis * (h2 @ W2), [N,64]@[64,40] ----------------
__global__ __launch_bounds__(256) void k_gemm2(const float* __restrict__ W2) {
    __shared__ float hs[32][HID + 1];   // pad -> conflict-free
    __shared__ float ws[HID * NCLS];    // 10 KB
    int tid = threadIdx.x;
    int rowBase = blockIdx.x * 32;

    for (int j = tid; j < 32 * HID; j += 256) {
        int r = j >> 6, c = j & 63;
        hs[r][c] = g_h2[(size_t)(rowBase + r) * HID + c];
    }
    for (int j = tid; j < HID * NCLS; j += 256) ws[j] = W2[j];
    __syncthreads();

    int row = tid >> 3;        // 0..31
    int cj = tid & 7;          // cols cj + 8u, u<5
    float acc[5] = {0.f, 0.f, 0.f, 0.f, 0.f};
    #pragma unroll 4
    for (int k = 0; k < HID; k++) {
        float a = hs[row][k];
        #pragma unroll
        for (int u = 0; u < 5; u++)
            acc[u] += a * ws[k * NCLS + cj + 8 * u];
    }
    float d = g_dis[rowBase + row];
    #pragma unroll
    for (int u = 0; u < 5; u++)
        g_g[(size_t)(rowBase + row) * NCLS + cj + 8 * u] = d * acc[u];
}

// ---------------- Agg2: out = dis*(self + sum nbr g_g) + b2 ----------------
__global__ __launch_bounds__(256) void k_agg2(const float* __restrict__ b2,
                                              float* __restrict__ out) {
    int gwarp = (blockIdx.x * blockDim.x + threadIdx.x) >> 5;
    int lane = threadIdx.x & 31;
    if (gwarp >= NN) return;
    int node = gwarp;

    size_t base = (size_t)node * NCLS;
    float a0 = g_g[base + lane];
    float a1 = (lane < 8) ? g_g[base + 32 + lane] : 0.f;

    int beg = g_off[node], end = g_off[node + 1];
    for (int e = beg; e < end; ++e) {
        int s = g_srcs[e];
        size_t sb = (size_t)s * NCLS;
        a0 += g_g[sb + lane];
        if (lane < 8) a1 += g_g[sb + 32 + lane];
    }

    float di = g_dis[node];
    out[base + lane] = di * a0 + b2[lane];
    if (lane < 8) out[base + 32 + lane] = di * a1 + b2[32 + lane];
}

// ---------------- launch ----------------
extern "C" void kernel_launch(void* const* d_in, const int* in_sizes, int n_in,
                              void* d_out, int out_size) {
    const float* x    = (const float*)d_in[0];
    const void*  eidx = d_in[1];
    const float* W1   = (const float*)d_in[2];
    const float* b1   = (const float*)d_in[3];
    const float* W2   = (const float*)d_in[4];
    const float* b2   = (const float*)d_in[5];
    float* out = (float*)d_out;

    // dtype probe + CSR build + norm
    k_probe<<<1, 1>>>((const int*)eidx);
    k_init_deg<<<(NN + 255) / 256, 256>>>();
    k_count<<<(EE + 255) / 256, 256>>>(eidx);
    k_scan1<<<NB_SCAN, SCAN_B>>>();
    k_scan2<<<1, 256>>>();
    k_scan3<<<(NN + 255) / 256, 256>>>();
    k_fill<<<(EE + 255) / 256, 256>>>(eidx);

    // Layer 1
    k_gemm1<<<NN / 32, 256>>>(x, W1);
    k_agg1<<<NN / 8, 256>>>(b1);

    // Layer 2
    k_gemm2<<<NN / 32, 256>>>(W2);
    k_agg2<<<NN / 8, 256>>>(b2, out);
}

// round 3
// speedup vs baseline: 1.0817x; 1.0817x over previous
#include <cuda_runtime.h>
#include <cuda_fp16.h>
#include <math.h>

typedef unsigned long long ull;

#define NN   100000
#define EE   1600000
#define INC  128
#define HID  64
#define NCLS 40

#define SCAN_B 512
#define NB_SCAN ((NN + SCAN_B - 1) / SCAN_B)   // 196

// ---------------- device scratch ----------------
__device__ int    g_is64;
__device__ int    g_deg[NN];
__device__ float  g_dis[NN];
__device__ int    g_off[NN + 1];
__device__ int    g_pos[NN];
__device__ int    g_srcs[EE];
__device__ __half g_hh[(size_t)NN * HID];   // fp16 dis-scaled x@W1
__device__ float  g_h2[(size_t)NN * HID];   // relu(agg1 + b1), fp32
__device__ float  g_g[(size_t)NN * NCLS];   // dis-scaled h2@W2, fp32
__device__ int    g_bsum[256];
__device__ int    g_bsumx[256];

// ---------------- f32x2 helpers ----------------
__device__ __forceinline__ ull splat2(float a) {
    ull r; asm("mov.b64 %0, {%1, %1};" : "=l"(r) : "f"(a)); return r;
}
__device__ __forceinline__ ull fma2(ull a, ull b, ull c) {
    asm("fma.rn.f32x2 %0, %1, %2, %0;" : "+l"(c) : "l"(a), "l"(b)); return c;
}
__device__ __forceinline__ float2 up2(ull v) {
    float2 f; asm("mov.b64 {%0, %1}, %2;" : "=f"(f.x), "=f"(f.y) : "l"(v)); return f;
}

// ---------------- init deg + dtype probe ----------------
__global__ void k_init(const int* __restrict__ e32) {
    int i = blockIdx.x * blockDim.x + threadIdx.x;
    if (i < NN) g_deg[i] = 0;
    if (i == 0) {
        // int64 LE with values < 2^31 -> odd words all zero.
        int all0 = 1;
        for (int j = 0; j < 64; j++)
            if (e32[2 * j + 1] != 0) { all0 = 0; break; }
        g_is64 = all0;
    }
}

__device__ __forceinline__ int load_idx(const void* eidx, size_t pos, int is64) {
    if (is64) return (int)((const long long*)eidx)[pos];
    return ((const int*)eidx)[pos];
}

__global__ void k_count(const void* __restrict__ eidx) {
    int e = blockIdx.x * blockDim.x + threadIdx.x;
    if (e >= EE) return;
    int d = load_idx(eidx, (size_t)EE + e, g_is64);
    if ((unsigned)d < NN) atomicAdd(&g_deg[d], 1);
}

__global__ void k_scan1() {
    __shared__ int s[SCAN_B];
    int tid = threadIdx.x;
    int i = blockIdx.x * SCAN_B + tid;
    int v = (i < NN) ? g_deg[i] : 0;
    s[tid] = v;
    __syncthreads();
    for (int o = 1; o < SCAN_B; o <<= 1) {
        int t = 0;
        if (tid >= o) t = s[tid - o];
        __syncthreads();
        s[tid] += t;
        __syncthreads();
    }
    if (i < NN) g_off[i] = s[tid] - v;
    if (tid == SCAN_B - 1) g_bsum[blockIdx.x] = s[tid];
}

__global__ void k_scan2() {
    __shared__ int s[256];
    int tid = threadIdx.x;
    int v = (tid < NB_SCAN) ? g_bsum[tid] : 0;
    s[tid] = v;
    __syncthreads();
    for (int o = 1; o < 256; o <<= 1) {
        int t = 0;
        if (tid >= o) t = s[tid - o];
        __syncthreads();
        s[tid] += t;
        __syncthreads();
    }
    g_bsumx[tid] = s[tid] - v;
}

__global__ void k_scan3() {
    int i = blockIdx.x * blockDim.x + threadIdx.x;
    if (i < NN) {
        int o = g_off[i] + g_bsumx[i >> 9];
        g_off[i] = o;
        g_pos[i] = o;
        g_dis[i] = rsqrtf((float)(g_deg[i] + 1));
    }
    if (i == 0) g_off[NN] = EE;
}

__global__ void k_fill(const void* __restrict__ eidx) {
    int e = blockIdx.x * blockDim.x + threadIdx.x;
    if (e >= EE) return;
    int is64 = g_is64;
    int s = load_idx(eidx, (size_t)e, is64);
    int d = load_idx(eidx, (size_t)EE + e, is64);
    if ((unsigned)d < NN && (unsigned)s < NN) {
        int p = atomicAdd(&g_pos[d], 1);
        if ((unsigned)p < EE) g_srcs[p] = s;
    }
}

// ---------------- GEMM1: g_hh = fp16(dis * (x @ W1)), row-per-thread, f32x2 ----------------
__global__ __launch_bounds__(128) void k_gemm1(const float* __restrict__ x,
                                               const float* __restrict__ W1) {
    // W1 as [128][64] floats -> [128][16] ulonglong2 (each = 4 floats = 2 f32x2 pairs)
    __shared__ ulonglong2 ws[INC * HID / 4];   // 32 KB
    int tid = threadIdx.x;
    const ulonglong2* w16 = (const ulonglong2*)W1;
    #pragma unroll
    for (int j = tid; j < INC * HID / 4; j += 128) ws[j] = w16[j];
    __syncthreads();

    int row = blockIdx.x * 128 + tid;
    if (row >= NN) return;

    ull acc[32];
    #pragma unroll
    for (int i = 0; i < 32; i++) acc[i] = 0ULL;

    const float4* xr = (const float4*)(x + (size_t)row * INC);
    #pragma unroll 1
    for (int kc = 0; kc < 8; kc++) {
        float4 a4[4];
        #pragma unroll
        for (int i = 0; i < 4; i++) a4[i] = xr[kc * 4 + i];
        const float* a = (const float*)a4;
        #pragma unroll
        for (int i = 0; i < 16; i++) {
            int k = kc * 16 + i;
            ull as = splat2(a[i]);
            #pragma unroll
            for (int q = 0; q < 16; q++) {     // 16 ulonglong2 = 64 cols
                ulonglong2 b = ws[k * 16 + q];
                acc[2 * q]     = fma2(as, b.x, acc[2 * q]);
                acc[2 * q + 1] = fma2(as, b.y, acc[2 * q + 1]);
            }
        }
    }

    float di = g_dis[row];
    uint4* dst = (uint4*)(g_hh + (size_t)row * HID);   // 8 x uint4 = 128 B
    #pragma unroll
    for (int q = 0; q < 8; q++) {
        uint4 o;
        #pragma unroll
        for (int j = 0; j < 4; j++) {
            float2 f = up2(acc[4 * q + j]);
            __half2 h = __floats2half2_rn(f.x * di, f.y * di);
            ((unsigned*)&o)[j] = *(unsigned*)&h;
        }
        dst[q] = o;
    }
}

// ---------------- Agg1: h2 = relu(dis*(self + sum nbr hh) + b1), 2 edges/warp ----------------
__global__ __launch_bounds__(256) void k_agg1(const float* __restrict__ b1) {
    int gwarp = (blockIdx.x * blockDim.x + threadIdx.x) >> 5;
    if (gwarp >= NN) return;
    int node = gwarp;
    int lane = threadIdx.x & 31;
    int half = lane >> 4;       // 0: even edges, 1: odd edges
    int l16  = lane & 15;       // 16 lanes x 8B = 128B fp16 row

    const uint2* hh = (const uint2*)g_hh;   // 16 uint2 per row
    float4 acc = make_float4(0.f, 0.f, 0.f, 0.f);

    if (half == 0) {            // self term once
        uint2 v = hh[(size_t)node * 16 + l16];
        float2 f01 = __half22float2(*(__half2*)&v.x);
        float2 f23 = __half22float2(*(__half2*)&v.y);
        acc.x = f01.x; acc.y = f01.y; acc.z = f23.x; acc.w = f23.y;
    }

    int beg = g_off[node], end = g_off[node + 1];
    for (int e = beg + half; e < end; e += 2) {
        int s = g_srcs[e];
        uint2 v = hh[(size_t)s * 16 + l16];
        float2 f01 = __half22float2(*(__half2*)&v.x);
        float2 f23 = __half22float2(*(__half2*)&v.y);
        acc.x += f01.x; acc.y += f01.y; acc.z += f23.x; acc.w += f23.y;
    }

    acc.x += __shfl_down_sync(0xffffffffu, acc.x, 16);
    acc.y += __shfl_down_sync(0xffffffffu, acc.y, 16);
    acc.z += __shfl_down_sync(0xffffffffu, acc.z, 16);
    acc.w += __shfl_down_sync(0xffffffffu, acc.w, 16);

    if (half == 0) {
        float di = g_dis[node];
        float4 b = ((const float4*)b1)[l16];
        float4 r;
        r.x = fmaxf(fmaf(di, acc.x, b.x), 0.f);
        r.y = fmaxf(fmaf(di, acc.y, b.y), 0.f);
        r.z = fmaxf(fmaf(di, acc.z, b.z), 0.f);
        r.w = fmaxf(fmaf(di, acc.w, b.w), 0.f);
        ((float4*)g_h2)[(size_t)node * 16 + l16] = r;
    }
}

// ---------------- GEMM2: g_g = dis * (h2 @ W2), row-per-thread, f32x2 ----------------
__global__ __launch_bounds__(128) void k_gemm2(const float* __restrict__ W2) {
    // W2 [64][40] floats -> [64][10] ulonglong2
    __shared__ ulonglong2 ws[HID * NCLS / 4];   // 10 KB
    int tid = threadIdx.x;
    const ulonglong2* w16 = (const ulonglong2*)W2;
    #pragma unroll
    for (int j = tid; j < HID * NCLS / 4; j += 128) ws[j] = w16[j];
    __syncthreads();

    int row = blockIdx.x * 128 + tid;
    if (row >= NN) return;

    ull acc[20];
    #pragma unroll
    for (int i = 0; i < 20; i++) acc[i] = 0ULL;

    const float4* hr = (const float4*)(g_h2 + (size_t)row * HID);
    #pragma unroll 1
    for (int kc = 0; kc < 4; kc++) {
        float4 a4[4];
        #pragma unroll
        for (int i = 0; i < 4; i++) a4[i] = hr[kc * 4 + i];
        const float* a = (const float*)a4;
        #pragma unroll
        for (int i = 0; i < 16; i++) {
            int k = kc * 16 + i;
            ull as = splat2(a[i]);
            #pragma unroll
            for (int q = 0; q < 10; q++) {
                ulonglong2 b = ws[k * 10 + q];
                acc[2 * q]     = fma2(as, b.x, acc[2 * q]);
                acc[2 * q + 1] = fma2(as, b.y, acc[2 * q + 1]);
            }
        }
    }

    float di = g_dis[row];
    float4* dst = (float4*)(g_g + (size_t)row * NCLS);   // 10 float4
    #pragma unroll
    for (int q = 0; q < 10; q++) {
        float2 f0 = up2(acc[2 * q]);
        float2 f1 = up2(acc[2 * q + 1]);
        dst[q] = make_float4(f0.x * di, f0.y * di, f1.x * di, f1.y * di);
    }
}

// ---------------- Agg2: out = dis*(self + sum nbr g) + b2, 3 edges/warp ----------------
__global__ __launch_bounds__(256) void k_agg2(const float* __restrict__ b2,
                                              float* __restrict__ out) {
    int gwarp = (blockIdx.x * blockDim.x + threadIdx.x) >> 5;
    if (gwarp >= NN) return;
    int node = gwarp;
    int lane = threadIdx.x & 31;
    int grp = lane / 10;            // 0,1,2 active; 3 for lanes 30,31
    int li  = lane - grp * 10;      // 10 lanes x float4 = 160B row

    const float4* gg = (const float4*)g_g;   // 10 float4 per row
    float4 acc = make_float4(0.f, 0.f, 0.f, 0.f);

    int beg = g_off[node], end = g_off[node + 1];
    if (grp == 0) {                 // self term once
        float4 v = gg[(size_t)node * 10 + li];
        acc.x = v.x; acc.y = v.y; acc.z = v.z; acc.w = v.w;
    }
    if (grp < 3) {
        for (int e = beg + grp; e < end; e += 3) {
            int s = g_srcs[e];
            float4 v = gg[(size_t)s * 10 + li];
            acc.x += v.x; acc.y += v.y; acc.z += v.z; acc.w += v.w;
        }
    }

    float4 t1, t2;
    t1.x = __shfl_down_sync(0xffffffffu, acc.x, 10);
    t1.y = __shfl_down_sync(0xffffffffu, acc.y, 10);
    t1.z = __shfl_down_sync(0xffffffffu, acc.z, 10);
    t1.w = __shfl_down_sync(0xffffffffu, acc.w, 10);
    t2.x = __shfl_down_sync(0xffffffffu, acc.x, 20);
    t2.y = __shfl_down_sync(0xffffffffu, acc.y, 20);
    t2.z = __shfl_down_sync(0xffffffffu, acc.z, 20);
    t2.w = __shfl_down_sync(0xffffffffu, acc.w, 20);

    if (grp == 0) {
        float di = g_dis[node];
        float4 b = ((const float4*)b2)[li];
        float4 r;
        r.x = fmaf(di, acc.x + t1.x + t2.x, b.x);
        r.y = fmaf(di, acc.y + t1.y + t2.y, b.y);
        r.z = fmaf(di, acc.z + t1.z + t2.z, b.z);
        r.w = fmaf(di, acc.w + t1.w + t2.w, b.w);
        ((float4*)out)[(size_t)node * 10 + li] = r;
    }
}

// ---------------- launch ----------------
extern "C" void kernel_launch(void* const* d_in, const int* in_sizes, int n_in,
                              void* d_out, int out_size) {
    const float* x    = (const float*)d_in[0];
    const void*  eidx = d_in[1];
    const float* W1   = (const float*)d_in[2];
    const float* b1   = (const float*)d_in[3];
    const float* W2   = (const float*)d_in[4];
    const float* b2   = (const float*)d_in[5];
    float* out = (float*)d_out;

    k_init<<<(NN + 255) / 256, 256>>>((const int*)eidx);
    k_count<<<(EE + 255) / 256, 256>>>(eidx);
    k_scan1<<<NB_SCAN, SCAN_B>>>();
    k_scan2<<<1, 256>>>();
    k_scan3<<<(NN + 255) / 256, 256>>>();
    k_fill<<<(EE + 255) / 256, 256>>>(eidx);

    k_gemm1<<<(NN + 127) / 128, 128>>>(x, W1);
    k_agg1<<<NN / 8, 256>>>(b1);

    k_gemm2<<<(NN + 127) / 128, 128>>>(W2);
    k_agg2<<<NN / 8, 256>>>(b2, out);
}

// round 4
// speedup vs baseline: 1.1222x; 1.0375x over previous
#include <cuda_runtime.h>
#include <cuda_fp16.h>
#include <math.h>

typedef unsigned long long ull;

#define NN   100000
#define EE   1600000
#define INC  128
#define HID  64
#define NCLS 40

#define SCAN_B 512
#define NB_SCAN ((NN + SCAN_B - 1) / SCAN_B)   // 196

// ---------------- device scratch ----------------
__device__ int      g_is64;
__device__ int      g_deg[NN];
__device__ float    g_dis[NN];
__device__ int      g_off[NN + 1];
__device__ int      g_pos[NN];
__device__ int      g_srcs[EE];
__device__ unsigned g_pub[NB_SCAN];
__device__ __half   g_hh[(size_t)NN * HID];    // fp16 dis-scaled x@W1
__device__ float    g_h2[(size_t)NN * HID];    // relu(agg1 + b1), fp32
__device__ __half   g_gh[(size_t)NN * NCLS];   // fp16 dis-scaled h2@W2

// ---------------- f32x2 helpers ----------------
__device__ __forceinline__ ull splat2(float a) {
    ull r; asm("mov.b64 %0, {%1, %1};" : "=l"(r) : "f"(a)); return r;
}
__device__ __forceinline__ ull fma2(ull a, ull b, ull c) {
    asm("fma.rn.f32x2 %0, %1, %2, %0;" : "+l"(c) : "l"(a), "l"(b)); return c;
}
__device__ __forceinline__ float2 up2(ull v) {
    float2 f; asm("mov.b64 {%0, %1}, %2;" : "=f"(f.x), "=f"(f.y) : "l"(v)); return f;
}

// ---------------- init: zero deg, reset scan state, dtype probe ----------------
__global__ void k_init(const int* __restrict__ e32) {
    int i = blockIdx.x * blockDim.x + threadIdx.x;
    if (i < NN) g_deg[i] = 0;
    if (i < NB_SCAN) g_pub[i] = 0u;
    if (i == 0) {
        int all0 = 1;
        for (int j = 0; j < 64; j++)
            if (e32[2 * j + 1] != 0) { all0 = 0; break; }
        g_is64 = all0;
    }
}

// ---------------- count: 4 edges per thread ----------------
__global__ void k_count(const void* __restrict__ eidx) {
    int t = blockIdx.x * blockDim.x + threadIdx.x;
    if (t >= EE / 4) return;
    int d0, d1, d2, d3;
    if (g_is64) {
        const longlong2* p = (const longlong2*)eidx + (size_t)EE / 2 + (size_t)t * 2;
        longlong2 a = p[0], b = p[1];
        d0 = (int)a.x; d1 = (int)a.y; d2 = (int)b.x; d3 = (int)b.y;
    } else {
        int4 d = ((const int4*)eidx)[(size_t)EE / 4 + t];
        d0 = d.x; d1 = d.y; d2 = d.z; d3 = d.w;
    }
    if ((unsigned)d0 < NN) atomicAdd(&g_deg[d0], 1);
    if ((unsigned)d1 < NN) atomicAdd(&g_deg[d1], 1);
    if ((unsigned)d2 < NN) atomicAdd(&g_deg[d2], 1);
    if ((unsigned)d3 < NN) atomicAdd(&g_deg[d3], 1);
}

// ---------------- single-pass scan with decoupled lookback ----------------
__global__ __launch_bounds__(SCAN_B) void k_scan() {
    __shared__ int s[SCAN_B];
    int tid = threadIdx.x;
    int b = blockIdx.x;
    int i = b * SCAN_B + tid;
    int v = (i < NN) ? g_deg[i] : 0;
    s[tid] = v;
    __syncthreads();
    for (int o = 1; o < SCAN_B; o <<= 1) {
        int t = 0;
        if (tid >= o) t = s[tid - o];
        __syncthreads();
        s[tid] += t;
        __syncthreads();
    }
    int incl = s[tid];

    if (tid == SCAN_B - 1)
        atomicExch(&g_pub[b], 0x80000000u | (unsigned)incl);

    int pre = 0;
    if (tid < b) {
        unsigned u;
        do { u = atomicAdd(&g_pub[tid], 0u); } while (!(u & 0x80000000u));
        pre = (int)(u & 0x7fffffffu);
    }
    __syncthreads();
    s[tid] = pre;
    __syncthreads();
    #pragma unroll
    for (int o = SCAN_B / 2; o > 0; o >>= 1) {
        if (tid < o) s[tid] += s[tid + o];
        __syncthreads();
    }
    int blockoff = s[0];

    if (i < NN) {
        int o = blockoff + incl - v;
        g_off[i] = o;
        g_pos[i] = o;
        g_dis[i] = rsqrtf((float)(v + 1));
    }
    if (b == 0 && tid == 0) g_off[NN] = EE;
}

// ---------------- fill: 4 edges per thread ----------------
__global__ void k_fill(const void* __restrict__ eidx) {
    int t = blockIdx.x * blockDim.x + threadIdx.x;
    if (t >= EE / 4) return;
    int s0, s1, s2, s3, d0, d1, d2, d3;
    if (g_is64) {
        const longlong2* ps = (const longlong2*)eidx + (size_t)t * 2;
        const longlong2* pd = (const longlong2*)eidx + (size_t)EE / 2 + (size_t)t * 2;
        longlong2 a = ps[0], b = ps[1], c = pd[0], d = pd[1];
        s0 = (int)a.x; s1 = (int)a.y; s2 = (int)b.x; s3 = (int)b.y;
        d0 = (int)c.x; d1 = (int)c.y; d2 = (int)d.x; d3 = (int)d.y;
    } else {
        int4 sv = ((const int4*)eidx)[t];
        int4 dv = ((const int4*)eidx)[(size_t)EE / 4 + t];
        s0 = sv.x; s1 = sv.y; s2 = sv.z; s3 = sv.w;
        d0 = dv.x; d1 = dv.y; d2 = dv.z; d3 = dv.w;
    }
    if ((unsigned)d0 < NN && (unsigned)s0 < NN) { int p = atomicAdd(&g_pos[d0], 1); if ((unsigned)p < EE) g_srcs[p] = s0; }
    if ((unsigned)d1 < NN && (unsigned)s1 < NN) { int p = atomicAdd(&g_pos[d1], 1); if ((unsigned)p < EE) g_srcs[p] = s1; }
    if ((unsigned)d2 < NN && (unsigned)s2 < NN) { int p = atomicAdd(&g_pos[d2], 1); if ((unsigned)p < EE) g_srcs[p] = s2; }
    if ((unsigned)d3 < NN && (unsigned)s3 < NN) { int p = atomicAdd(&g_pos[d3], 1); if ((unsigned)p < EE) g_srcs[p] = s3; }
}

// ---------------- GEMM1: g_hh = fp16(dis * (x @ W1)) ----------------
__global__ __launch_bounds__(128) void k_gemm1(const float* __restrict__ x,
                                               const float* __restrict__ W1) {
    __shared__ ulonglong2 ws[INC * HID / 4];
    int tid = threadIdx.x;
    const ulonglong2* w16 = (const ulonglong2*)W1;
    #pragma unroll
    for (int j = tid; j < INC * HID / 4; j += 128) ws[j] = w16[j];
    __syncthreads();

    int row = blockIdx.x * 128 + tid;
    if (row >= NN) return;

    ull acc[32];
    #pragma unroll
    for (int i = 0; i < 32; i++) acc[i] = 0ULL;

    const float4* xr = (const float4*)(x + (size_t)row * INC);
    #pragma unroll 1
    for (int kc = 0; kc < 8; kc++) {
        float4 a4[4];
        #pragma unroll
        for (int i = 0; i < 4; i++) a4[i] = xr[kc * 4 + i];
        const float* a = (const float*)a4;
        #pragma unroll
        for (int i = 0; i < 16; i++) {
            int k = kc * 16 + i;
            ull as = splat2(a[i]);
            #pragma unroll
            for (int q = 0; q < 16; q++) {
                ulonglong2 b = ws[k * 16 + q];
                acc[2 * q]     = fma2(as, b.x, acc[2 * q]);
                acc[2 * q + 1] = fma2(as, b.y, acc[2 * q + 1]);
            }
        }
    }

    float di = g_dis[row];
    uint4* dst = (uint4*)(g_hh + (size_t)row * HID);
    #pragma unroll
    for (int q = 0; q < 8; q++) {
        uint4 o;
        #pragma unroll
        for (int j = 0; j < 4; j++) {
            float2 f = up2(acc[4 * q + j]);
            __half2 h = __floats2half2_rn(f.x * di, f.y * di);
            ((unsigned*)&o)[j] = *(unsigned*)&h;
        }
        dst[q] = o;
    }
}

// ---------------- Agg1: 4 edges/warp, fp16 gather, fp32 accumulate ----------------
__global__ __launch_bounds__(256) void k_agg1(const float* __restrict__ b1) {
    int gwarp = (blockIdx.x * blockDim.x + threadIdx.x) >> 5;
    if (gwarp >= NN) return;
    int node = gwarp;
    int lane = threadIdx.x & 31;
    int grp = lane >> 3;
    int l8  = lane & 7;

    const uint4* hh = (const uint4*)g_hh;
    float acc[8];
    #pragma unroll
    for (int j = 0; j < 8; j++) acc[j] = 0.f;

    if (grp == 0) {
        uint4 v = hh[(size_t)node * 8 + l8];
        float2 f;
        f = __half22float2(*(__half2*)&v.x); acc[0] = f.x; acc[1] = f.y;
        f = __half22float2(*(__half2*)&v.y); acc[2] = f.x; acc[3] = f.y;
        f = __half22float2(*(__half2*)&v.z); acc[4] = f.x; acc[5] = f.y;
        f = __half22float2(*(__half2*)&v.w); acc[6] = f.x; acc[7] = f.y;
    }

    int beg = g_off[node], end = g_off[node + 1];
    for (int e = beg + grp; e < end; e += 4) {
        int s = g_srcs[e];
        uint4 v = hh[(size_t)s * 8 + l8];
        float2 f;
        f = __half22float2(*(__half2*)&v.x); acc[0] += f.x; acc[1] += f.y;
        f = __half22float2(*(__half2*)&v.y); acc[2] += f.x; acc[3] += f.y;
        f = __half22float2(*(__half2*)&v.z); acc[4] += f.x; acc[5] += f.y;
        f = __half22float2(*(__half2*)&v.w); acc[6] += f.x; acc[7] += f.y;
    }

    // two-round tree: +16 then +8 (sums all 4 groups into lanes 0-7)
    #pragma unroll
    for (int j = 0; j < 8; j++)
        acc[j] += __shfl_down_sync(0xffffffffu, acc[j], 16);
    #pragma unroll
    for (int j = 0; j < 8; j++)
        acc[j] += __shfl_down_sync(0xffffffffu, acc[j], 8);

    if (grp == 0) {
        float di = g_dis[node];
        float4 b0 = ((const float4*)b1)[l8 * 2];
        float4 b4 = ((const float4*)b1)[l8 * 2 + 1];
        float4* o = (float4*)(g_h2 + (size_t)node * HID + l8 * 8);
        o[0] = make_float4(fmaxf(fmaf(di, acc[0], b0.x), 0.f),
                           fmaxf(fmaf(di, acc[1], b0.y), 0.f),
                           fmaxf(fmaf(di, acc[2], b0.z), 0.f),
                           fmaxf(fmaf(di, acc[3], b0.w), 0.f));
        o[1] = make_float4(fmaxf(fmaf(di, acc[4], b4.x), 0.f),
                           fmaxf(fmaf(di, acc[5], b4.y), 0.f),
                           fmaxf(fmaf(di, acc[6], b4.z), 0.f),
                           fmaxf(fmaf(di, acc[7], b4.w), 0.f));
    }
}

// ---------------- GEMM2: g_gh = fp16(dis * (h2 @ W2)) ----------------
__global__ __launch_bounds__(128) void k_gemm2(const float* __restrict__ W2) {
    __shared__ ulonglong2 ws[HID * NCLS / 4];
    int tid = threadIdx.x;
    const ulonglong2* w16 = (const ulonglong2*)W2;
    #pragma unroll
    for (int j = tid; j < HID * NCLS / 4; j += 128) ws[j] = w16[j];
    __syncthreads();

    int row = blockIdx.x * 128 + tid;
    if (row >= NN) return;

    ull acc[20];
    #pragma unroll
    for (int i = 0; i < 20; i++) acc[i] = 0ULL;

    const float4* hr = (const float4*)(g_h2 + (size_t)row * HID);
    #pragma unroll 1
    for (int kc = 0; kc < 4; kc++) {
        float4 a4[4];
        #pragma unroll
        for (int i = 0; i < 4; i++) a4[i] = hr[kc * 4 + i];
        const float* a = (const float*)a4;
        #pragma unroll
        for (int i = 0; i < 16; i++) {
            int k = kc * 16 + i;
            ull as = splat2(a[i]);
            #pragma unroll
            for (int q = 0; q < 10; q++) {
                ulonglong2 b = ws[k * 10 + q];
                acc[2 * q]     = fma2(as, b.x, acc[2 * q]);
                acc[2 * q + 1] = fma2(as, b.y, acc[2 * q + 1]);
            }
        }
    }

    float di = g_dis[row];
    uint2* dst = (uint2*)(g_gh + (size_t)row * NCLS);
    #pragma unroll
    for (int q = 0; q < 10; q++) {
        float2 f0 = up2(acc[2 * q]);
        float2 f1 = up2(acc[2 * q + 1]);
        __half2 h0 = __floats2half2_rn(f0.x * di, f0.y * di);
        __half2 h1 = __floats2half2_rn(f1.x * di, f1.y * di);
        dst[q] = make_uint2(*(unsigned*)&h0, *(unsigned*)&h1);
    }
}

// ---------------- Agg2: 3 edges/warp, fp16 gather, fp32 out ----------------
__global__ __launch_bounds__(256) void k_agg2(const float* __restrict__ b2,
                                              float* __restrict__ out) {
    int gwarp = (blockIdx.x * blockDim.x + threadIdx.x) >> 5;
    if (gwarp >= NN) return;
    int node = gwarp;
    int lane = threadIdx.x & 31;
    int grp = lane / 10;
    int li  = lane - grp * 10;

    const uint2* gg = (const uint2*)g_gh;
    float acc[4] = {0.f, 0.f, 0.f, 0.f};

    if (grp == 0) {
        uint2 v = gg[(size_t)node * 10 + li];
        float2 f;
        f = __half22float2(*(__half2*)&v.x); acc[0] = f.x; acc[1] = f.y;
        f = __half22float2(*(__half2*)&v.y); acc[2] = f.x; acc[3] = f.y;
    }

    int beg = g_off[node], end = g_off[node + 1];
    if (grp < 3) {
        for (int e = beg + grp; e < end; e += 3) {
            int s = g_srcs[e];
            uint2 v = gg[(size_t)s * 10 + li];
            float2 f;
            f = __half22float2(*(__half2*)&v.x); acc[0] += f.x; acc[1] += f.y;
            f = __half22float2(*(__half2*)&v.y); acc[2] += f.x; acc[3] += f.y;
        }
    }

    #pragma unroll
    for (int j = 0; j < 4; j++) {
        float t1 = __shfl_down_sync(0xffffffffu, acc[j], 10);
        float t2 = __shfl_down_sync(0xffffffffu, acc[j], 20);
        acc[j] += t1 + t2;
    }

    if (grp == 0) {
        float di = g_dis[node];
        float4 b = ((const float4*)b2)[li];
        float4 r;
        r.x = fmaf(di, acc[0], b.x);
        r.y = fmaf(di, acc[1], b.y);
        r.z = fmaf(di, acc[2], b.z);
        r.w = fmaf(di, acc[3], b.w);
        ((float4*)out)[(size_t)node * 10 + li] = r;
    }
}

// ---------------- launch ----------------
extern "C" void kernel_launch(void* const* d_in, const int* in_sizes, int n_in,
                              void* d_out, int out_size) {
    const float* x    = (const float*)d_in[0];
    const void*  eidx = d_in[1];
    const float* W1   = (const float*)d_in[2];
    const float* b1   = (const float*)d_in[3];
    const float* W2   = (const float*)d_in[4];
    const float* b2   = (const float*)d_in[5];
    float* out = (float*)d_out;

    k_init<<<(NN + 255) / 256, 256>>>((const int*)eidx);
    k_count<<<(EE / 4 + 255) / 256, 256>>>(eidx);
    k_scan<<<NB_SCAN, SCAN_B>>>();
    k_fill<<<(EE / 4 + 255) / 256, 256>>>(eidx);

    k_gemm1<<<(NN + 127) / 128, 128>>>(x, W1);
    k_agg1<<<NN / 8, 256>>>(b1);

    k_gemm2<<<(NN + 127) / 128, 128>>>(W2);
    k_agg2<<<NN / 8, 256>>>(b2, out);
}

// round 5
// speedup vs baseline: 1.1415x; 1.0172x over previous
#include <cuda_runtime.h>
#include <cuda_fp16.h>
#include <math.h>

typedef unsigned long long ull;

#define NN   100000
#define EE   1600000
#define INC  128
#define HID  64
#define NCLS 40

#define SCAN_B 512
#define NB_SCAN ((NN + SCAN_B - 1) / SCAN_B)   // 196

// ---------------- device scratch ----------------
__device__ int      g_is64;
__device__ int      g_deg[NN];
__device__ float    g_dis[NN];
__device__ int      g_off[NN + 1];
__device__ int      g_pos[NN];
__device__ int      g_srcs[EE];
__device__ unsigned g_pub[NB_SCAN];
__device__ __half   g_hh[(size_t)NN * HID];    // fp16 UNSCALED x@W1
__device__ float    g_h2[(size_t)NN * HID];    // relu(agg1 + b1), fp32
__device__ __half   g_gh[(size_t)NN * NCLS];   // fp16 dis-scaled h2@W2

// ---------------- f32x2 helpers ----------------
__device__ __forceinline__ ull splat2(float a) {
    ull r; asm("mov.b64 %0, {%1, %1};" : "=l"(r) : "f"(a)); return r;
}
__device__ __forceinline__ ull fma2(ull a, ull b, ull c) {
    asm("fma.rn.f32x2 %0, %1, %2, %0;" : "+l"(c) : "l"(a), "l"(b)); return c;
}
__device__ __forceinline__ float2 up2(ull v) {
    float2 f; asm("mov.b64 {%0, %1}, %2;" : "=f"(f.x), "=f"(f.y) : "l"(v)); return f;
}

// ---------------- init: zero deg, reset scan state, dtype probe ----------------
__global__ void k_init(const int* __restrict__ e32) {
    int i = blockIdx.x * blockDim.x + threadIdx.x;
    if (i < NN) g_deg[i] = 0;
    if (i < NB_SCAN) g_pub[i] = 0u;
    if (i == 0) {
        int all0 = 1;
        for (int j = 0; j < 64; j++)
            if (e32[2 * j + 1] != 0) { all0 = 0; break; }
        g_is64 = all0;
    }
}

// ---------------- count: 8 edges per thread (RED, no return use) ----------------
__global__ void k_count(const void* __restrict__ eidx) {
    int t = blockIdx.x * blockDim.x + threadIdx.x;
    if (t >= EE / 8) return;
    int d[8];
    if (g_is64) {
        const longlong2* p = (const longlong2*)eidx + (size_t)EE / 2 + (size_t)t * 4;
        #pragma unroll
        for (int j = 0; j < 4; j++) {
            longlong2 a = p[j];
            d[2 * j] = (int)a.x; d[2 * j + 1] = (int)a.y;
        }
    } else {
        const int4* p = (const int4*)eidx + (size_t)EE / 4 + (size_t)t * 2;
        int4 a = p[0], b = p[1];
        d[0] = a.x; d[1] = a.y; d[2] = a.z; d[3] = a.w;
        d[4] = b.x; d[5] = b.y; d[6] = b.z; d[7] = b.w;
    }
    #pragma unroll
    for (int j = 0; j < 8; j++)
        if ((unsigned)d[j] < NN) atomicAdd(&g_deg[d[j]], 1);
}

// ---------------- single-pass scan with decoupled lookback ----------------
__global__ __launch_bounds__(SCAN_B) void k_scan() {
    __shared__ int s[SCAN_B];
    int tid = threadIdx.x;
    int b = blockIdx.x;
    int i = b * SCAN_B + tid;
    int v = (i < NN) ? g_deg[i] : 0;
    s[tid] = v;
    __syncthreads();
    for (int o = 1; o < SCAN_B; o <<= 1) {
        int t = 0;
        if (tid >= o) t = s[tid - o];
        __syncthreads();
        s[tid] += t;
        __syncthreads();
    }
    int incl = s[tid];

    if (tid == SCAN_B - 1)
        atomicExch(&g_pub[b], 0x80000000u | (unsigned)incl);

    int pre = 0;
    if (tid < b) {
        unsigned u;
        do { u = atomicAdd(&g_pub[tid], 0u); } while (!(u & 0x80000000u));
        pre = (int)(u & 0x7fffffffu);
    }
    __syncthreads();
    s[tid] = pre;
    __syncthreads();
    #pragma unroll
    for (int o = SCAN_B / 2; o > 0; o >>= 1) {
        if (tid < o) s[tid] += s[tid + o];
        __syncthreads();
    }
    int blockoff = s[0];

    if (i < NN) {
        int o = blockoff + incl - v;
        g_off[i] = o;
        g_pos[i] = o;
        g_dis[i] = rsqrtf((float)(v + 1));
    }
    if (b == 0 && tid == 0) g_off[NN] = EE;
}

// ---------------- fill: 8 edges per thread ----------------
__global__ void k_fill(const void* __restrict__ eidx) {
    int t = blockIdx.x * blockDim.x + threadIdx.x;
    if (t >= EE / 8) return;
    int sv[8], dv[8];
    if (g_is64) {
        const longlong2* ps = (const longlong2*)eidx + (size_t)t * 4;
        const longlong2* pd = (const longlong2*)eidx + (size_t)EE / 2 + (size_t)t * 4;
        #pragma unroll
        for (int j = 0; j < 4; j++) {
            longlong2 a = ps[j], c = pd[j];
            sv[2 * j] = (int)a.x; sv[2 * j + 1] = (int)a.y;
            dv[2 * j] = (int)c.x; dv[2 * j + 1] = (int)c.y;
        }
    } else {
        const int4* ps = (const int4*)eidx + (size_t)t * 2;
        const int4* pd = (const int4*)eidx + (size_t)EE / 4 + (size_t)t * 2;
        int4 a = ps[0], b = ps[1], c = pd[0], d = pd[1];
        sv[0] = a.x; sv[1] = a.y; sv[2] = a.z; sv[3] = a.w;
        sv[4] = b.x; sv[5] = b.y; sv[6] = b.z; sv[7] = b.w;
        dv[0] = c.x; dv[1] = c.y; dv[2] = c.z; dv[3] = c.w;
        dv[4] = d.x; dv[5] = d.y; dv[6] = d.z; dv[7] = d.w;
    }
    int p[8];
    #pragma unroll
    for (int j = 0; j < 8; j++) {
        p[j] = -1;
        if ((unsigned)dv[j] < NN && (unsigned)sv[j] < NN)
            p[j] = atomicAdd(&g_pos[dv[j]], 1);
    }
    #pragma unroll
    for (int j = 0; j < 8; j++)
        if ((unsigned)p[j] < EE) g_srcs[p[j]] = sv[j];
}

// ---------------- GEMM1: g_hh = fp16(x @ W1), NO dis (CSR-independent) ----------------
__global__ __launch_bounds__(128) void k_gemm1(const float* __restrict__ x,
                                               const float* __restrict__ W1) {
    __shared__ ulonglong2 ws[INC * HID / 4];
    int tid = threadIdx.x;
    const ulonglong2* w16 = (const ulonglong2*)W1;
    #pragma unroll
    for (int j = tid; j < INC * HID / 4; j += 128) ws[j] = w16[j];
    __syncthreads();

    int row = blockIdx.x * 128 + tid;
    if (row >= NN) return;

    ull acc[32];
    #pragma unroll
    for (int i = 0; i < 32; i++) acc[i] = 0ULL;

    const float4* xr = (const float4*)(x + (size_t)row * INC);
    #pragma unroll 1
    for (int kc = 0; kc < 8; kc++) {
        float4 a4[4];
        #pragma unroll
        for (int i = 0; i < 4; i++) a4[i] = xr[kc * 4 + i];
        const float* a = (const float*)a4;
        #pragma unroll
        for (int i = 0; i < 16; i++) {
            int k = kc * 16 + i;
            ull as = splat2(a[i]);
            #pragma unroll
            for (int q = 0; q < 16; q++) {
                ulonglong2 b = ws[k * 16 + q];
                acc[2 * q]     = fma2(as, b.x, acc[2 * q]);
                acc[2 * q + 1] = fma2(as, b.y, acc[2 * q + 1]);
            }
        }
    }

    uint4* dst = (uint4*)(g_hh + (size_t)row * HID);
    #pragma unroll
    for (int q = 0; q < 8; q++) {
        uint4 o;
        #pragma unroll
        for (int j = 0; j < 4; j++) {
            float2 f = up2(acc[4 * q + j]);
            __half2 h = __floats2half2_rn(f.x, f.y);
            ((unsigned*)&o)[j] = *(unsigned*)&h;
        }
        dst[q] = o;
    }
}

// ---------------- Agg1: 4 edges/warp, dis[src] applied at gather ----------------
__global__ __launch_bounds__(256) void k_agg1(const float* __restrict__ b1) {
    int gwarp = (blockIdx.x * blockDim.x + threadIdx.x) >> 5;
    if (gwarp >= NN) return;
    int node = gwarp;
    int lane = threadIdx.x & 31;
    int grp = lane >> 3;
    int l8  = lane & 7;

    const uint4* hh = (const uint4*)g_hh;
    float acc[8];
    #pragma unroll
    for (int j = 0; j < 8; j++) acc[j] = 0.f;

    float di = g_dis[node];
    if (grp == 0) {                    // self term: dis[node]*row(node)
        uint4 v = hh[(size_t)node * 8 + l8];
        float2 f;
        f = __half22float2(*(__half2*)&v.x); acc[0] = di * f.x; acc[1] = di * f.y;
        f = __half22float2(*(__half2*)&v.y); acc[2] = di * f.x; acc[3] = di * f.y;
        f = __half22float2(*(__half2*)&v.z); acc[4] = di * f.x; acc[5] = di * f.y;
        f = __half22float2(*(__half2*)&v.w); acc[6] = di * f.x; acc[7] = di * f.y;
    }

    int beg = g_off[node], end = g_off[node + 1];
    int e = beg + grp;
    int s = (e < end) ? g_srcs[e] : 0;
    while (e < end) {
        int e2 = e + 4;
        int s2 = (e2 < end) ? g_srcs[e2] : 0;       // prefetch next idx
        float ds = g_dis[s];
        uint4 v = hh[(size_t)s * 8 + l8];
        float2 f;
        f = __half22float2(*(__half2*)&v.x); acc[0] += ds * f.x; acc[1] += ds * f.y;
        f = __half22float2(*(__half2*)&v.y); acc[2] += ds * f.x; acc[3] += ds * f.y;
        f = __half22float2(*(__half2*)&v.z); acc[4] += ds * f.x; acc[5] += ds * f.y;
        f = __half22float2(*(__half2*)&v.w); acc[6] += ds * f.x; acc[7] += ds * f.y;
        s = s2; e = e2;
    }

    // two-round tree: +16 then +8 (sums all 4 groups into lanes 0-7)
    #pragma unroll
    for (int j = 0; j < 8; j++)
        acc[j] += __shfl_down_sync(0xffffffffu, acc[j], 16);
    #pragma unroll
    for (int j = 0; j < 8; j++)
        acc[j] += __shfl_down_sync(0xffffffffu, acc[j], 8);

    if (grp == 0) {
        float4 b0 = ((const float4*)b1)[l8 * 2];
        float4 b4 = ((const float4*)b1)[l8 * 2 + 1];
        float4* o = (float4*)(g_h2 + (size_t)node * HID + l8 * 8);
        o[0] = make_float4(fmaxf(fmaf(di, acc[0], b0.x), 0.f),
                           fmaxf(fmaf(di, acc[1], b0.y), 0.f),
                           fmaxf(fmaf(di, acc[2], b0.z), 0.f),
                           fmaxf(fmaf(di, acc[3], b0.w), 0.f));
        o[1] = make_float4(fmaxf(fmaf(di, acc[4], b4.x), 0.f),
                           fmaxf(fmaf(di, acc[5], b4.y), 0.f),
                           fmaxf(fmaf(di, acc[6], b4.z), 0.f),
                           fmaxf(fmaf(di, acc[7], b4.w), 0.f));
    }
}

// ---------------- GEMM2: g_gh = fp16(dis * (h2 @ W2)) ----------------
__global__ __launch_bounds__(128) void k_gemm2(const float* __restrict__ W2) {
    __shared__ ulonglong2 ws[HID * NCLS / 4];
    int tid = threadIdx.x;
    const ulonglong2* w16 = (const ulonglong2*)W2;
    #pragma unroll
    for (int j = tid; j < HID * NCLS / 4; j += 128) ws[j] = w16[j];
    __syncthreads();

    int row = blockIdx.x * 128 + tid;
    if (row >= NN) return;

    ull acc[20];
    #pragma unroll
    for (int i = 0; i < 20; i++) acc[i] = 0ULL;

    const float4* hr = (const float4*)(g_h2 + (size_t)row * HID);
    #pragma unroll 1
    for (int kc = 0; kc < 4; kc++) {
        float4 a4[4];
        #pragma unroll
        for (int i = 0; i < 4; i++) a4[i] = hr[kc * 4 + i];
        const float* a = (const float*)a4;
        #pragma unroll
        for (int i = 0; i < 16; i++) {
            int k = kc * 16 + i;
            ull as = splat2(a[i]);
            #pragma unroll
            for (int q = 0; q < 10; q++) {
                ulonglong2 b = ws[k * 10 + q];
                acc[2 * q]     = fma2(as, b.x, acc[2 * q]);
                acc[2 * q + 1] = fma2(as, b.y, acc[2 * q + 1]);
            }
        }
    }

    float di = g_dis[row];
    uint2* dst = (uint2*)(g_gh + (size_t)row * NCLS);
    #pragma unroll
    for (int q = 0; q < 10; q++) {
        float2 f0 = up2(acc[2 * q]);
        float2 f1 = up2(acc[2 * q + 1]);
        __half2 h0 = __floats2half2_rn(f0.x * di, f0.y * di);
        __half2 h1 = __floats2half2_rn(f1.x * di, f1.y * di);
        dst[q] = make_uint2(*(unsigned*)&h0, *(unsigned*)&h1);
    }
}

// ---------------- Agg2: 3 edges/warp, fp16 gather, fp32 out ----------------
__global__ __launch_bounds__(256) void k_agg2(const float* __restrict__ b2,
                                              float* __restrict__ out) {
    int gwarp = (blockIdx.x * blockDim.x + threadIdx.x) >> 5;
    if (gwarp >= NN) return;
    int node = gwarp;
    int lane = threadIdx.x & 31;
    int grp = lane / 10;
    int li  = lane - grp * 10;

    const uint2* gg = (const uint2*)g_gh;
    float acc[4] = {0.f, 0.f, 0.f, 0.f};

    if (grp == 0) {
        uint2 v = gg[(size_t)node * 10 + li];
        float2 f;
        f = __half22float2(*(__half2*)&v.x); acc[0] = f.x; acc[1] = f.y;
        f = __half22float2(*(__half2*)&v.y); acc[2] = f.x; acc[3] = f.y;
    }

    int beg = g_off[node], end = g_off[node + 1];
    if (grp < 3) {
        int e = beg + grp;
        int s = (e < end) ? g_srcs[e] : 0;
        while (e < end) {
            int e2 = e + 3;
            int s2 = (e2 < end) ? g_srcs[e2] : 0;   // prefetch next idx
            uint2 v = gg[(size_t)s * 10 + li];
            float2 f;
            f = __half22float2(*(__half2*)&v.x); acc[0] += f.x; acc[1] += f.y;
            f = __half22float2(*(__half2*)&v.y); acc[2] += f.x; acc[3] += f.y;
            s = s2; e = e2;
        }
    }

    #pragma unroll
    for (int j = 0; j < 4; j++) {
        float t1 = __shfl_down_sync(0xffffffffu, acc[j], 10);
        float t2 = __shfl_down_sync(0xffffffffu, acc[j], 20);
        acc[j] += t1 + t2;
    }

    if (grp == 0) {
        float di = g_dis[node];
        float4 b = ((const float4*)b2)[li];
        float4 r;
        r.x = fmaf(di, acc[0], b.x);
        r.y = fmaf(di, acc[1], b.y);
        r.z = fmaf(di, acc[2], b.z);
        r.w = fmaf(di, acc[3], b.w);
        ((float4*)out)[(size_t)node * 10 + li] = r;
    }
}

// ---------------- launch ----------------
extern "C" void kernel_launch(void* const* d_in, const int* in_sizes, int n_in,
                              void* d_out, int out_size) {
    const float* x    = (const float*)d_in[0];
    const void*  eidx = d_in[1];
    const float* W1   = (const float*)d_in[2];
    const float* b1   = (const float*)d_in[3];
    const float* W2   = (const float*)d_in[4];
    const float* b2   = (const float*)d_in[5];
    float* out = (float*)d_out;

    // lazy side-stream (created once, before any capture; no device mem)
    static cudaStream_t s2 = nullptr;
    static cudaEvent_t evF = nullptr, evG = nullptr;
    static bool use2 = false;
    if (!s2) {
        use2 = (cudaStreamCreateWithFlags(&s2, cudaStreamNonBlocking) == cudaSuccess) &&
               (cudaEventCreateWithFlags(&evF, cudaEventDisableTiming) == cudaSuccess) &&
               (cudaEventCreateWithFlags(&evG, cudaEventDisableTiming) == cudaSuccess);
        if (!use2) s2 = (cudaStream_t)0x1;   // mark attempted
    }

    if (use2) {
        // fork: gemm1 (CSR-independent) runs concurrently with CSR build
        cudaEventRecord(evF, 0);
        cudaStreamWaitEvent(s2, evF, 0);
        k_gemm1<<<(NN + 127) / 128, 128, 0, s2>>>(x, W1);
        cudaEventRecord(evG, s2);

        k_init<<<(NN + 255) / 256, 256>>>((const int*)eidx);
        k_count<<<(EE / 8 + 255) / 256, 256>>>(eidx);
        k_scan<<<NB_SCAN, SCAN_B>>>();
        k_fill<<<(EE / 8 + 255) / 256, 256>>>(eidx);

        cudaStreamWaitEvent(0, evG, 0);      // join before agg1
    } else {
        k_init<<<(NN + 255) / 256, 256>>>((const int*)eidx);
        k_count<<<(EE / 8 + 255) / 256, 256>>>(eidx);
        k_scan<<<NB_SCAN, SCAN_B>>>();
        k_fill<<<(EE / 8 + 255) / 256, 256>>>(eidx);
        k_gemm1<<<(NN + 127) / 128, 128>>>(x, W1);
    }

    k_agg1<<<NN / 8, 256>>>(b1);
    k_gemm2<<<(NN + 127) / 128, 128>>>(W2);
    k_agg2<<<NN / 8, 256>>>(b2, out);
}

// round 6
// speedup vs baseline: 1.1664x; 1.0218x over previous
#include <cuda_runtime.h>
#include <cuda_fp16.h>
#include <math.h>

typedef unsigned long long ull;

#define NN   100000
#define EE   1600000
#define INC  128
#define HID  64
#define NCLS 40

#define SCAN_B 512
#define NB_SCAN ((NN + SCAN_B - 1) / SCAN_B)   // 196

// ---------------- device scratch ----------------
__device__ int      g_is64;
__device__ int      g_deg[NN];
__device__ float    g_dis[NN];
__device__ int      g_off[NN + 1];
__device__ int      g_pos[NN];
__device__ int      g_srcs[EE];
__device__ unsigned g_pub[NB_SCAN];
__device__ __half   g_hh[(size_t)NN * HID];    // fp16 dis-scaled x@W1
__device__ float    g_h2[(size_t)NN * HID];    // relu(agg1 + b1), fp32
__device__ __half   g_gh[(size_t)NN * NCLS];   // fp16 dis-scaled h2@W2

// ---------------- f32x2 helpers ----------------
__device__ __forceinline__ ull splat2(float a) {
    ull r; asm("mov.b64 %0, {%1, %1};" : "=l"(r) : "f"(a)); return r;
}
__device__ __forceinline__ ull fma2(ull a, ull b, ull c) {
    asm("fma.rn.f32x2 %0, %1, %2, %0;" : "+l"(c) : "l"(a), "l"(b)); return c;
}
__device__ __forceinline__ float2 up2(ull v) {
    float2 f; asm("mov.b64 {%0, %1}, %2;" : "=f"(f.x), "=f"(f.y) : "l"(v)); return f;
}

// ---------------- init: zero deg, reset scan state, dtype probe ----------------
__global__ void k_init(const int* __restrict__ e32) {
    int i = blockIdx.x * blockDim.x + threadIdx.x;
    if (i < NN) g_deg[i] = 0;
    if (i < NB_SCAN) g_pub[i] = 0u;
    if (i == 0) {
        int all0 = 1;
        for (int j = 0; j < 64; j++)
            if (e32[2 * j + 1] != 0) { all0 = 0; break; }
        g_is64 = all0;
    }
}

// ---------------- count: 8 edges per thread ----------------
__global__ void k_count(const void* __restrict__ eidx) {
    int t = blockIdx.x * blockDim.x + threadIdx.x;
    if (t >= EE / 8) return;
    int d[8];
    if (g_is64) {
        const longlong2* p = (const longlong2*)eidx + (size_t)EE / 2 + (size_t)t * 4;
        #pragma unroll
        for (int j = 0; j < 4; j++) {
            longlong2 a = p[j];
            d[2 * j] = (int)a.x; d[2 * j + 1] = (int)a.y;
        }
    } else {
        const int4* p = (const int4*)eidx + (size_t)EE / 4 + (size_t)t * 2;
        int4 a = p[0], b = p[1];
        d[0] = a.x; d[1] = a.y; d[2] = a.z; d[3] = a.w;
        d[4] = b.x; d[5] = b.y; d[6] = b.z; d[7] = b.w;
    }
    #pragma unroll
    for (int j = 0; j < 8; j++)
        if ((unsigned)d[j] < NN) atomicAdd(&g_deg[d[j]], 1);
}

// ---------------- single-pass scan with decoupled lookback ----------------
__global__ __launch_bounds__(SCAN_B) void k_scan() {
    __shared__ int s[SCAN_B];
    int tid = threadIdx.x;
    int b = blockIdx.x;
    int i = b * SCAN_B + tid;
    int v = (i < NN) ? g_deg[i] : 0;
    s[tid] = v;
    __syncthreads();
    for (int o = 1; o < SCAN_B; o <<= 1) {
        int t = 0;
        if (tid >= o) t = s[tid - o];
        __syncthreads();
        s[tid] += t;
        __syncthreads();
    }
    int incl = s[tid];

    if (tid == SCAN_B - 1)
        atomicExch(&g_pub[b], 0x80000000u | (unsigned)incl);

    int pre = 0;
    if (tid < b) {
        unsigned u;
        do { u = atomicAdd(&g_pub[tid], 0u); } while (!(u & 0x80000000u));
        pre = (int)(u & 0x7fffffffu);
    }
    __syncthreads();
    s[tid] = pre;
    __syncthreads();
    #pragma unroll
    for (int o = SCAN_B / 2; o > 0; o >>= 1) {
        if (tid < o) s[tid] += s[tid + o];
        __syncthreads();
    }
    int blockoff = s[0];

    if (i < NN) {
        int o = blockoff + incl - v;
        g_off[i] = o;
        g_pos[i] = o;
        g_dis[i] = rsqrtf((float)(v + 1));
    }
    if (b == 0 && tid == 0) g_off[NN] = EE;
}

// ---------------- fill: 8 edges per thread ----------------
__global__ void k_fill(const void* __restrict__ eidx) {
    int t = blockIdx.x * blockDim.x + threadIdx.x;
    if (t >= EE / 8) return;
    int sv[8], dv[8];
    if (g_is64) {
        const longlong2* ps = (const longlong2*)eidx + (size_t)t * 4;
        const longlong2* pd = (const longlong2*)eidx + (size_t)EE / 2 + (size_t)t * 4;
        #pragma unroll
        for (int j = 0; j < 4; j++) {
            longlong2 a = ps[j], c = pd[j];
            sv[2 * j] = (int)a.x; sv[2 * j + 1] = (int)a.y;
            dv[2 * j] = (int)c.x; dv[2 * j + 1] = (int)c.y;
        }
    } else {
        const int4* ps = (const int4*)eidx + (size_t)t * 2;
        const int4* pd = (const int4*)eidx + (size_t)EE / 4 + (size_t)t * 2;
        int4 a = ps[0], b = ps[1], c = pd[0], d = pd[1];
        sv[0] = a.x; sv[1] = a.y; sv[2] = a.z; sv[3] = a.w;
        sv[4] = b.x; sv[5] = b.y; sv[6] = b.z; sv[7] = b.w;
        dv[0] = c.x; dv[1] = c.y; dv[2] = c.z; dv[3] = c.w;
        dv[4] = d.x; dv[5] = d.y; dv[6] = d.z; dv[7] = d.w;
    }
    int p[8];
    #pragma unroll
    for (int j = 0; j < 8; j++) {
        p[j] = -1;
        if ((unsigned)dv[j] < NN && (unsigned)sv[j] < NN)
            p[j] = atomicAdd(&g_pos[dv[j]], 1);
    }
    #pragma unroll
    for (int j = 0; j < 8; j++)
        if ((unsigned)p[j] < EE) g_srcs[p[j]] = sv[j];
}

// ---------------- GEMM1: g_hh = fp16(dis * (x @ W1)) ----------------
__global__ __launch_bounds__(128) void k_gemm1(const float* __restrict__ x,
                                               const float* __restrict__ W1) {
    __shared__ ulonglong2 ws[INC * HID / 4];
    int tid = threadIdx.x;
    const ulonglong2* w16 = (const ulonglong2*)W1;
    #pragma unroll
    for (int j = tid; j < INC * HID / 4; j += 128) ws[j] = w16[j];
    __syncthreads();

    int row = blockIdx.x * 128 + tid;
    if (row >= NN) return;

    ull acc[32];
    #pragma unroll
    for (int i = 0; i < 32; i++) acc[i] = 0ULL;

    const float4* xr = (const float4*)(x + (size_t)row * INC);
    #pragma unroll 1
    for (int kc = 0; kc < 8; kc++) {
        float4 a4[4];
        #pragma unroll
        for (int i = 0; i < 4; i++) a4[i] = xr[kc * 4 + i];
        const float* a = (const float*)a4;
        #pragma unroll
        for (int i = 0; i < 16; i++) {
            int k = kc * 16 + i;
            ull as = splat2(a[i]);
            #pragma unroll
            for (int q = 0; q < 16; q++) {
                ulonglong2 b = ws[k * 16 + q];
                acc[2 * q]     = fma2(as, b.x, acc[2 * q]);
                acc[2 * q + 1] = fma2(as, b.y, acc[2 * q + 1]);
            }
        }
    }

    float di = g_dis[row];
    uint4* dst = (uint4*)(g_hh + (size_t)row * HID);
    #pragma unroll
    for (int q = 0; q < 8; q++) {
        uint4 o;
        #pragma unroll
        for (int j = 0; j < 4; j++) {
            float2 f = up2(acc[4 * q + j]);
            __half2 h = __floats2half2_rn(f.x * di, f.y * di);
            ((unsigned*)&o)[j] = *(unsigned*)&h;
        }
        dst[q] = o;
    }
}

// ---------------- Agg1: 4 edge-groups/warp, 2-deep pipelined gathers ----------------
__global__ __launch_bounds__(256) void k_agg1(const float* __restrict__ b1) {
    int gwarp = (blockIdx.x * blockDim.x + threadIdx.x) >> 5;
    if (gwarp >= NN) return;
    int node = gwarp;
    int lane = threadIdx.x & 31;
    int grp = lane >> 3;
    int l8  = lane & 7;

    const uint4* hh = (const uint4*)g_hh;
    float acc[8];
    #pragma unroll
    for (int j = 0; j < 8; j++) acc[j] = 0.f;

    if (grp == 0) {                    // self term (prescaled)
        uint4 v = hh[(size_t)node * 8 + l8];
        float2 f;
        f = __half22float2(*(__half2*)&v.x); acc[0] = f.x; acc[1] = f.y;
        f = __half22float2(*(__half2*)&v.y); acc[2] = f.x; acc[3] = f.y;
        f = __half22float2(*(__half2*)&v.z); acc[4] = f.x; acc[5] = f.y;
        f = __half22float2(*(__half2*)&v.w); acc[6] = f.x; acc[7] = f.y;
    }

    int beg = g_off[node], end = g_off[node + 1];
    int e = beg + grp;
    bool hA = e < end;
    bool hB = e + 4 < end;
    int sA = hA ? g_srcs[e] : 0;
    int sB = hB ? g_srcs[e + 4] : 0;

    while (hA) {
        int en = e + 8;
        bool hA2 = en < end, hB2 = en + 4 < end;
        int sA2 = hA2 ? g_srcs[en] : 0;
        int sB2 = hB2 ? g_srcs[en + 4] : 0;

        // both row loads issued before either is consumed (MLP=2)
        uint4 vA = hh[(size_t)sA * 8 + l8];
        uint4 vB = hB ? hh[(size_t)sB * 8 + l8] : make_uint4(0u, 0u, 0u, 0u);

        float2 f;
        f = __half22float2(*(__half2*)&vA.x); acc[0] += f.x; acc[1] += f.y;
        f = __half22float2(*(__half2*)&vA.y); acc[2] += f.x; acc[3] += f.y;
        f = __half22float2(*(__half2*)&vA.z); acc[4] += f.x; acc[5] += f.y;
        f = __half22float2(*(__half2*)&vA.w); acc[6] += f.x; acc[7] += f.y;
        f = __half22float2(*(__half2*)&vB.x); acc[0] += f.x; acc[1] += f.y;
        f = __half22float2(*(__half2*)&vB.y); acc[2] += f.x; acc[3] += f.y;
        f = __half22float2(*(__half2*)&vB.z); acc[4] += f.x; acc[5] += f.y;
        f = __half22float2(*(__half2*)&vB.w); acc[6] += f.x; acc[7] += f.y;

        hA = hA2; hB = hB2; sA = sA2; sB = sB2; e = en;
    }

    #pragma unroll
    for (int j = 0; j < 8; j++)
        acc[j] += __shfl_down_sync(0xffffffffu, acc[j], 16);
    #pragma unroll
    for (int j = 0; j < 8; j++)
        acc[j] += __shfl_down_sync(0xffffffffu, acc[j], 8);

    if (grp == 0) {
        float di = g_dis[node];
        float4 b0 = ((const float4*)b1)[l8 * 2];
        float4 b4 = ((const float4*)b1)[l8 * 2 + 1];
        float4* o = (float4*)(g_h2 + (size_t)node * HID + l8 * 8);
        o[0] = make_float4(fmaxf(fmaf(di, acc[0], b0.x), 0.f),
                           fmaxf(fmaf(di, acc[1], b0.y), 0.f),
                           fmaxf(fmaf(di, acc[2], b0.z), 0.f),
                           fmaxf(fmaf(di, acc[3], b0.w), 0.f));
        o[1] = make_float4(fmaxf(fmaf(di, acc[4], b4.x), 0.f),
                           fmaxf(fmaf(di, acc[5], b4.y), 0.f),
                           fmaxf(fmaf(di, acc[6], b4.z), 0.f),
                           fmaxf(fmaf(di, acc[7], b4.w), 0.f));
    }
}

// ---------------- GEMM2: g_gh = fp16(dis * (h2 @ W2)) ----------------
__global__ __launch_bounds__(128) void k_gemm2(const float* __restrict__ W2) {
    __shared__ ulonglong2 ws[HID * NCLS / 4];
    int tid = threadIdx.x;
    const ulonglong2* w16 = (const ulonglong2*)W2;
    #pragma unroll
    for (int j = tid; j < HID * NCLS / 4; j += 128) ws[j] = w16[j];
    __syncthreads();

    int row = blockIdx.x * 128 + tid;
    if (row >= NN) return;

    ull acc[20];
    #pragma unroll
    for (int i = 0; i < 20; i++) acc[i] = 0ULL;

    const float4* hr = (const float4*)(g_h2 + (size_t)row * HID);
    #pragma unroll 1
    for (int kc = 0; kc < 4; kc++) {
        float4 a4[4];
        #pragma unroll
        for (int i = 0; i < 4; i++) a4[i] = hr[kc * 4 + i];
        const float* a = (const float*)a4;
        #pragma unroll
        for (int i = 0; i < 16; i++) {
            int k = kc * 16 + i;
            ull as = splat2(a[i]);
            #pragma unroll
            for (int q = 0; q < 10; q++) {
                ulonglong2 b = ws[k * 10 + q];
                acc[2 * q]     = fma2(as, b.x, acc[2 * q]);
                acc[2 * q + 1] = fma2(as, b.y, acc[2 * q + 1]);
            }
        }
    }

    float di = g_dis[row];
    uint2* dst = (uint2*)(g_gh + (size_t)row * NCLS);
    #pragma unroll
    for (int q = 0; q < 10; q++) {
        float2 f0 = up2(acc[2 * q]);
        float2 f1 = up2(acc[2 * q + 1]);
        __half2 h0 = __floats2half2_rn(f0.x * di, f0.y * di);
        __half2 h1 = __floats2half2_rn(f1.x * di, f1.y * di);
        dst[q] = make_uint2(*(unsigned*)&h0, *(unsigned*)&h1);
    }
}

// ---------------- Agg2: 3 edge-groups/warp, 2-deep pipelined gathers ----------------
__global__ __launch_bounds__(256) void k_agg2(const float* __restrict__ b2,
                                              float* __restrict__ out) {
    int gwarp = (blockIdx.x * blockDim.x + threadIdx.x) >> 5;
    if (gwarp >= NN) return;
    int node = gwarp;
    int lane = threadIdx.x & 31;
    int grp = lane / 10;
    int li  = lane - grp * 10;

    const uint2* gg = (const uint2*)g_gh;
    float acc[4] = {0.f, 0.f, 0.f, 0.f};

    if (grp == 0) {
        uint2 v = gg[(size_t)node * 10 + li];
        float2 f;
        f = __half22float2(*(__half2*)&v.x); acc[0] = f.x; acc[1] = f.y;
        f = __half22float2(*(__half2*)&v.y); acc[2] = f.x; acc[3] = f.y;
    }

    int beg = g_off[node], end = g_off[node + 1];
    if (grp < 3) {
        int e = beg + grp;
        bool hA = e < end;
        bool hB = e + 3 < end;
        int sA = hA ? g_srcs[e] : 0;
        int sB = hB ? g_srcs[e + 3] : 0;

        while (hA) {
            int en = e + 6;
            bool hA2 = en < end, hB2 = en + 3 < end;
            int sA2 = hA2 ? g_srcs[en] : 0;
            int sB2 = hB2 ? g_srcs[en + 3] : 0;

            uint2 vA = gg[(size_t)sA * 10 + li];
            uint2 vB = hB ? gg[(size_t)sB * 10 + li] : make_uint2(0u, 0u);

            float2 f;
            f = __half22float2(*(__half2*)&vA.x); acc[0] += f.x; acc[1] += f.y;
            f = __half22float2(*(__half2*)&vA.y); acc[2] += f.x; acc[3] += f.y;
            f = __half22float2(*(__half2*)&vB.x); acc[0] += f.x; acc[1] += f.y;
            f = __half22float2(*(__half2*)&vB.y); acc[2] += f.x; acc[3] += f.y;

            hA = hA2; hB = hB2; sA = sA2; sB = sB2; e = en;
        }
    }

    #pragma unroll
    for (int j = 0; j < 4; j++) {
        float t1 = __shfl_down_sync(0xffffffffu, acc[j], 10);
        float t2 = __shfl_down_sync(0xffffffffu, acc[j], 20);
        acc[j] += t1 + t2;
    }

    if (grp == 0) {
        float di = g_dis[node];
        float4 b = ((const float4*)b2)[li];
        float4 r;
        r.x = fmaf(di, acc[0], b.x);
        r.y = fmaf(di, acc[1], b.y);
        r.z = fmaf(di, acc[2], b.z);
        r.w = fmaf(di, acc[3], b.w);
        ((float4*)out)[(size_t)node * 10 + li] = r;
    }
}

// ---------------- launch ----------------
extern "C" void kernel_launch(void* const* d_in, const int* in_sizes, int n_in,
                              void* d_out, int out_size) {
    const float* x    = (const float*)d_in[0];
    const void*  eidx = d_in[1];
    const float* W1   = (const float*)d_in[2];
    const float* b1   = (const float*)d_in[3];
    const float* W2   = (const float*)d_in[4];
    const float* b2   = (const float*)d_in[5];
    float* out = (float*)d_out;

    static cudaStream_t s2 = nullptr;
    static cudaEvent_t evD = nullptr, evG = nullptr;
    static bool use2 = false;
    if (!s2) {
        use2 = (cudaStreamCreateWithFlags(&s2, cudaStreamNonBlocking) == cudaSuccess) &&
               (cudaEventCreateWithFlags(&evD, cudaEventDisableTiming) == cudaSuccess) &&
               (cudaEventCreateWithFlags(&evG, cudaEventDisableTiming) == cudaSuccess);
        if (!use2) s2 = (cudaStream_t)0x1;
    }

    k_init<<<(NN + 255) / 256, 256>>>((const int*)eidx);
    k_count<<<(EE / 8 + 255) / 256, 256>>>(eidx);
    k_scan<<<NB_SCAN, SCAN_B>>>();                      // dis ready here

    if (use2) {
        cudaEventRecord(evD, 0);
        cudaStreamWaitEvent(s2, evD, 0);
        k_gemm1<<<(NN + 127) / 128, 128, 0, s2>>>(x, W1);  // ∥ fill
        cudaEventRecord(evG, s2);

        k_fill<<<(EE / 8 + 255) / 256, 256>>>(eidx);

        cudaStreamWaitEvent(0, evG, 0);
    } else {
        k_gemm1<<<(NN + 127) / 128, 128>>>(x, W1);
        k_fill<<<(EE / 8 + 255) / 256, 256>>>(eidx);
    }

    k_agg1<<<NN / 8, 256>>>(b1);
    k_gemm2<<<(NN + 127) / 128, 128>>>(W2);
    k_agg2<<<NN / 8, 256>>>(b2, out);
}

// round 7
// speedup vs baseline: 1.3463x; 1.1542x over previous
#include <cuda_runtime.h>
#include <cuda_fp16.h>
#include <math.h>

typedef unsigned long long ull;

#define NN   100000
#define EE   1600000
#define INC  128
#define HID  64
#define NCLS 40

#define SCAN_B 512
#define NB_SCAN ((NN + SCAN_B - 1) / SCAN_B)   // 196

// ---------------- device scratch ----------------
__device__ int      g_is64;
__device__ int      g_deg[NN];
__device__ float    g_dis[NN];
__device__ int      g_off[NN + 1];
__device__ int      g_pos[NN];
__device__ int      g_srcs[EE];
__device__ unsigned g_pub[NB_SCAN];
__device__ __half   g_hh[(size_t)NN * HID];    // fp16 dis-scaled x@W1
__device__ float    g_h2[(size_t)NN * HID];    // relu(agg1 + b1), fp32
__device__ __half   g_gh[(size_t)NN * NCLS];   // fp16 dis-scaled h2@W2

// ---------------- f32x2 helpers ----------------
__device__ __forceinline__ ull splat2(float a) {
    ull r; asm("mov.b64 %0, {%1, %1};" : "=l"(r) : "f"(a)); return r;
}
__device__ __forceinline__ ull fma2(ull a, ull b, ull c) {
    asm("fma.rn.f32x2 %0, %1, %2, %0;" : "+l"(c) : "l"(a), "l"(b)); return c;
}
__device__ __forceinline__ float2 up2(ull v) {
    float2 f; asm("mov.b64 {%0, %1}, %2;" : "=f"(f.x), "=f"(f.y) : "l"(v)); return f;
}

// ---------------- init: zero deg, reset scan state, dtype probe ----------------
__global__ void k_init(const int* __restrict__ e32) {
    int i = blockIdx.x * blockDim.x + threadIdx.x;
    if (i < NN) g_deg[i] = 0;
    if (i < NB_SCAN) g_pub[i] = 0u;
    if (i == 0) {
        int all0 = 1;
        for (int j = 0; j < 64; j++)
            if (e32[2 * j + 1] != 0) { all0 = 0; break; }
        g_is64 = all0;
    }
}

// ---------------- count: 8 edges per thread ----------------
__global__ void k_count(const void* __restrict__ eidx) {
    int t = blockIdx.x * blockDim.x + threadIdx.x;
    if (t >= EE / 8) return;
    int d[8];
    if (g_is64) {
        const longlong2* p = (const longlong2*)eidx + (size_t)EE / 2 + (size_t)t * 4;
        #pragma unroll
        for (int j = 0; j < 4; j++) {
            longlong2 a = p[j];
            d[2 * j] = (int)a.x; d[2 * j + 1] = (int)a.y;
        }
    } else {
        const int4* p = (const int4*)eidx + (size_t)EE / 4 + (size_t)t * 2;
        int4 a = p[0], b = p[1];
        d[0] = a.x; d[1] = a.y; d[2] = a.z; d[3] = a.w;
        d[4] = b.x; d[5] = b.y; d[6] = b.z; d[7] = b.w;
    }
    #pragma unroll
    for (int j = 0; j < 8; j++)
        if ((unsigned)d[j] < NN) atomicAdd(&g_deg[d[j]], 1);
}

// ---------------- single-pass scan with decoupled lookback ----------------
__global__ __launch_bounds__(SCAN_B) void k_scan() {
    __shared__ int s[SCAN_B];
    int tid = threadIdx.x;
    int b = blockIdx.x;
    int i = b * SCAN_B + tid;
    int v = (i < NN) ? g_deg[i] : 0;
    s[tid] = v;
    __syncthreads();
    for (int o = 1; o < SCAN_B; o <<= 1) {
        int t = 0;
        if (tid >= o) t = s[tid - o];
        __syncthreads();
        s[tid] += t;
        __syncthreads();
    }
    int incl = s[tid];

    if (tid == SCAN_B - 1)
        atomicExch(&g_pub[b], 0x80000000u | (unsigned)incl);

    int pre = 0;
    if (tid < b) {
        unsigned u;
        do { u = atomicAdd(&g_pub[tid], 0u); } while (!(u & 0x80000000u));
        pre = (int)(u & 0x7fffffffu);
    }
    __syncthreads();
    s[tid] = pre;
    __syncthreads();
    #pragma unroll
    for (int o = SCAN_B / 2; o > 0; o >>= 1) {
        if (tid < o) s[tid] += s[tid + o];
        __syncthreads();
    }
    int blockoff = s[0];

    if (i < NN) {
        int o = blockoff + incl - v;
        g_off[i] = o;
        g_pos[i] = o;
        g_dis[i] = rsqrtf((float)(v + 1));
    }
    if (b == 0 && tid == 0) g_off[NN] = EE;
}

// ---------------- fill: 8 edges per thread ----------------
__global__ void k_fill(const void* __restrict__ eidx) {
    int t = blockIdx.x * blockDim.x + threadIdx.x;
    if (t >= EE / 8) return;
    int sv[8], dv[8];
    if (g_is64) {
        const longlong2* ps = (const longlong2*)eidx + (size_t)t * 4;
        const longlong2* pd = (const longlong2*)eidx + (size_t)EE / 2 + (size_t)t * 4;
        #pragma unroll
        for (int j = 0; j < 4; j++) {
            longlong2 a = ps[j], c = pd[j];
            sv[2 * j] = (int)a.x; sv[2 * j + 1] = (int)a.y;
            dv[2 * j] = (int)c.x; dv[2 * j + 1] = (int)c.y;
        }
    } else {
        const int4* ps = (const int4*)eidx + (size_t)t * 2;
        const int4* pd = (const int4*)eidx + (size_t)EE / 4 + (size_t)t * 2;
        int4 a = ps[0], b = ps[1], c = pd[0], d = pd[1];
        sv[0] = a.x; sv[1] = a.y; sv[2] = a.z; sv[3] = a.w;
        sv[4] = b.x; sv[5] = b.y; sv[6] = b.z; sv[7] = b.w;
        dv[0] = c.x; dv[1] = c.y; dv[2] = c.z; dv[3] = c.w;
        dv[4] = d.x; dv[5] = d.y; dv[6] = d.z; dv[7] = d.w;
    }
    int p[8];
    #pragma unroll
    for (int j = 0; j < 8; j++) {
        p[j] = -1;
        if ((unsigned)dv[j] < NN && (unsigned)sv[j] < NN)
            p[j] = atomicAdd(&g_pos[dv[j]], 1);
    }
    #pragma unroll
    for (int j = 0; j < 8; j++)
        if ((unsigned)p[j] < EE) g_srcs[p[j]] = sv[j];
}

// ---------------- GEMM1: g_hh = fp16(dis * (x @ W1)), 8x8 register tile ----------------
// block = 128 threads = 16 row-groups (8 rows) x 8 col-groups (8 cols); tile 128x64
__global__ __launch_bounds__(128) void k_gemm1(const float* __restrict__ x,
                                               const float* __restrict__ W1) {
    __shared__ ull ws[INC * 32];          // [128 k][32 ull] = 64 cols, 32 KB
    int tid = threadIdx.x;
    {
        const ulonglong2* w16 = (const ulonglong2*)W1;
        ulonglong2* wd = (ulonglong2*)ws;
        #pragma unroll
        for (int j = tid; j < INC * HID / 4; j += 128) wd[j] = w16[j];
    }
    __syncthreads();

    int colg = tid & 7;
    int rowg = tid >> 3;
    int row0 = blockIdx.x * 128 + rowg * 8;

    bool ok[8];
    const float4* xr[8];
    #pragma unroll
    for (int i = 0; i < 8; i++) {
        ok[i] = (row0 + i) < NN;
        xr[i] = (const float4*)(x + (size_t)(ok[i] ? row0 + i : 0) * INC);
    }

    ull acc[8][4];
    #pragma unroll
    for (int i = 0; i < 8; i++)
        #pragma unroll
        for (int j = 0; j < 4; j++) acc[i][j] = 0ULL;

    const ulonglong2* wsv = (const ulonglong2*)ws;
    #pragma unroll 2
    for (int kc = 0; kc < 32; kc++) {
        float4 a4[8];
        #pragma unroll
        for (int i = 0; i < 8; i++) a4[i] = xr[i][kc];   // 8 rows, 4 k each
        #pragma unroll
        for (int kk = 0; kk < 4; kk++) {
            int k = kc * 4 + kk;
            ulonglong2 b01 = wsv[k * 16 + colg * 2];
            ulonglong2 b23 = wsv[k * 16 + colg * 2 + 1];
            #pragma unroll
            for (int i = 0; i < 8; i++) {
                ull as = splat2(((const float*)&a4[i])[kk]);
                acc[i][0] = fma2(as, b01.x, acc[i][0]);
                acc[i][1] = fma2(as, b01.y, acc[i][1]);
                acc[i][2] = fma2(as, b23.x, acc[i][2]);
                acc[i][3] = fma2(as, b23.y, acc[i][3]);
            }
        }
    }

    #pragma unroll
    for (int i = 0; i < 8; i++) {
        if (!ok[i]) continue;
        float di = g_dis[row0 + i];
        uint2 o0, o1;
        float2 f;
        __half2 h;
        f = up2(acc[i][0]); h = __floats2half2_rn(f.x * di, f.y * di); o0.x = *(unsigned*)&h;
        f = up2(acc[i][1]); h = __floats2half2_rn(f.x * di, f.y * di); o0.y = *(unsigned*)&h;
        f = up2(acc[i][2]); h = __floats2half2_rn(f.x * di, f.y * di); o1.x = *(unsigned*)&h;
        f = up2(acc[i][3]); h = __floats2half2_rn(f.x * di, f.y * di); o1.y = *(unsigned*)&h;
        uint4* dst = (uint4*)(g_hh + (size_t)(row0 + i) * HID + colg * 8);
        *dst = make_uint4(o0.x, o0.y, o1.x, o1.y);
    }
}

// ---------------- Agg1: 4 edge-groups/warp, 2-deep pipelined gathers ----------------
__global__ __launch_bounds__(256) void k_agg1(const float* __restrict__ b1) {
    int gwarp = (blockIdx.x * blockDim.x + threadIdx.x) >> 5;
    if (gwarp >= NN) return;
    int node = gwarp;
    int lane = threadIdx.x & 31;
    int grp = lane >> 3;
    int l8  = lane & 7;

    const uint4* hh = (const uint4*)g_hh;
    float acc[8];
    #pragma unroll
    for (int j = 0; j < 8; j++) acc[j] = 0.f;

    if (grp == 0) {                    // self term (prescaled)
        uint4 v = hh[(size_t)node * 8 + l8];
        float2 f;
        f = __half22float2(*(__half2*)&v.x); acc[0] = f.x; acc[1] = f.y;
        f = __half22float2(*(__half2*)&v.y); acc[2] = f.x; acc[3] = f.y;
        f = __half22float2(*(__half2*)&v.z); acc[4] = f.x; acc[5] = f.y;
        f = __half22float2(*(__half2*)&v.w); acc[6] = f.x; acc[7] = f.y;
    }

    int beg = g_off[node], end = g_off[node + 1];
    int e = beg + grp;
    bool hA = e < end;
    bool hB = e + 4 < end;
    int sA = hA ? g_srcs[e] : 0;
    int sB = hB ? g_srcs[e + 4] : 0;

    while (hA) {
        int en = e + 8;
        bool hA2 = en < end, hB2 = en + 4 < end;
        int sA2 = hA2 ? g_srcs[en] : 0;
        int sB2 = hB2 ? g_srcs[en + 4] : 0;

        uint4 vA = hh[(size_t)sA * 8 + l8];
        uint4 vB = hB ? hh[(size_t)sB * 8 + l8] : make_uint4(0u, 0u, 0u, 0u);

        float2 f;
        f = __half22float2(*(__half2*)&vA.x); acc[0] += f.x; acc[1] += f.y;
        f = __half22float2(*(__half2*)&vA.y); acc[2] += f.x; acc[3] += f.y;
        f = __half22float2(*(__half2*)&vA.z); acc[4] += f.x; acc[5] += f.y;
        f = __half22float2(*(__half2*)&vA.w); acc[6] += f.x; acc[7] += f.y;
        f = __half22float2(*(__half2*)&vB.x); acc[0] += f.x; acc[1] += f.y;
        f = __half22float2(*(__half2*)&vB.y); acc[2] += f.x; acc[3] += f.y;
        f = __half22float2(*(__half2*)&vB.z); acc[4] += f.x; acc[5] += f.y;
        f = __half22float2(*(__half2*)&vB.w); acc[6] += f.x; acc[7] += f.y;

        hA = hA2; hB = hB2; sA = sA2; sB = sB2; e = en;
    }

    #pragma unroll
    for (int j = 0; j < 8; j++)
        acc[j] += __shfl_down_sync(0xffffffffu, acc[j], 16);
    #pragma unroll
    for (int j = 0; j < 8; j++)
        acc[j] += __shfl_down_sync(0xffffffffu, acc[j], 8);

    if (grp == 0) {
        float di = g_dis[node];
        float4 b0 = ((const float4*)b1)[l8 * 2];
        float4 b4 = ((const float4*)b1)[l8 * 2 + 1];
        float4* o = (float4*)(g_h2 + (size_t)node * HID + l8 * 8);
        o[0] = make_float4(fmaxf(fmaf(di, acc[0], b0.x), 0.f),
                           fmaxf(fmaf(di, acc[1], b0.y), 0.f),
                           fmaxf(fmaf(di, acc[2], b0.z), 0.f),
                           fmaxf(fmaf(di, acc[3], b0.w), 0.f));
        o[1] = make_float4(fmaxf(fmaf(di, acc[4], b4.x), 0.f),
                           fmaxf(fmaf(di, acc[5], b4.y), 0.f),
                           fmaxf(fmaf(di, acc[6], b4.z), 0.f),
                           fmaxf(fmaf(di, acc[7], b4.w), 0.f));
    }
}

// ---------------- GEMM2: g_gh = fp16(dis * (h2 @ W2)), 8x10 register tile ----------------
// block = 128 threads = 32 row-groups (8 rows) x 4 col-groups (10 cols); tile 256x40
__global__ __launch_bounds__(128) void k_gemm2(const float* __restrict__ W2) {
    __shared__ ull ws[HID * 20];          // [64 k][20 ull] = 40 cols, 10 KB
    int tid = threadIdx.x;
    {
        const ulonglong2* w16 = (const ulonglong2*)W2;
        ulonglong2* wd = (ulonglong2*)ws;
        #pragma unroll
        for (int j = tid; j < HID * NCLS / 4; j += 128) wd[j] = w16[j];
    }
    __syncthreads();

    int colg = tid & 3;
    int rowg = tid >> 2;
    int row0 = blockIdx.x * 256 + rowg * 8;

    bool ok[8];
    const float4* hr[8];
    #pragma unroll
    for (int i = 0; i < 8; i++) {
        ok[i] = (row0 + i) < NN;
        hr[i] = (const float4*)(g_h2 + (size_t)(ok[i] ? row0 + i : 0) * HID);
    }

    ull acc[8][5];
    #pragma unroll
    for (int i = 0; i < 8; i++)
        #pragma unroll
        for (int j = 0; j < 5; j++) acc[i][j] = 0ULL;

    #pragma unroll 2
    for (int kc = 0; kc < 16; kc++) {
        float4 a4[8];
        #pragma unroll
        for (int i = 0; i < 8; i++) a4[i] = hr[i][kc];
        #pragma unroll
        for (int kk = 0; kk < 4; kk++) {
            int k = kc * 4 + kk;
            ull b[5];
            #pragma unroll
            for (int j = 0; j < 5; j++) b[j] = ws[k * 20 + colg * 5 + j];
            #pragma unroll
            for (int i = 0; i < 8; i++) {
                ull as = splat2(((const float*)&a4[i])[kk]);
                #pragma unroll
                for (int j = 0; j < 5; j++)
                    acc[i][j] = fma2(as, b[j], acc[i][j]);
            }
        }
    }

    #pragma unroll
    for (int i = 0; i < 8; i++) {
        if (!ok[i]) continue;
        float di = g_dis[row0 + i];
        unsigned* dst = (unsigned*)(g_gh + (size_t)(row0 + i) * NCLS + colg * 10);
        #pragma unroll
        for (int j = 0; j < 5; j++) {
            float2 f = up2(acc[i][j]);
            __half2 h = __floats2half2_rn(f.x * di, f.y * di);
            dst[j] = *(unsigned*)&h;
        }
    }
}

// ---------------- Agg2: 3 edge-groups/warp, 2-deep pipelined gathers ----------------
__global__ __launch_bounds__(256) void k_agg2(const float* __restrict__ b2,
                                              float* __restrict__ out) {
    int gwarp = (blockIdx.x * blockDim.x + threadIdx.x) >> 5;
    if (gwarp >= NN) return;
    int node = gwarp;
    int lane = threadIdx.x & 31;
    int grp = lane / 10;
    int li  = lane - grp * 10;

    const uint2* gg = (const uint2*)g_gh;
    float acc[4] = {0.f, 0.f, 0.f, 0.f};

    if (grp == 0) {
        uint2 v = gg[(size_t)node * 10 + li];
        float2 f;
        f = __half22float2(*(__half2*)&v.x); acc[0] = f.x; acc[1] = f.y;
        f = __half22float2(*(__half2*)&v.y); acc[2] = f.x; acc[3] = f.y;
    }

    int beg = g_off[node], end = g_off[node + 1];
    if (grp < 3) {
        int e = beg + grp;
        bool hA = e < end;
        bool hB = e + 3 < end;
        int sA = hA ? g_srcs[e] : 0;
        int sB = hB ? g_srcs[e + 3] : 0;

        while (hA) {
            int en = e + 6;
            bool hA2 = en < end, hB2 = en + 3 < end;
            int sA2 = hA2 ? g_srcs[en] : 0;
            int sB2 = hB2 ? g_srcs[en + 3] : 0;

            uint2 vA = gg[(size_t)sA * 10 + li];
            uint2 vB = hB ? gg[(size_t)sB * 10 + li] : make_uint2(0u, 0u);

            float2 f;
            f = __half22float2(*(__half2*)&vA.x); acc[0] += f.x; acc[1] += f.y;
            f = __half22float2(*(__half2*)&vA.y); acc[2] += f.x; acc[3] += f.y;
            f = __half22float2(*(__half2*)&vB.x); acc[0] += f.x; acc[1] += f.y;
            f = __half22float2(*(__half2*)&vB.y); acc[2] += f.x; acc[3] += f.y;

            hA = hA2; hB = hB2; sA = sA2; sB = sB2; e = en;
        }
    }

    #pragma unroll
    for (int j = 0; j < 4; j++) {
        float t1 = __shfl_down_sync(0xffffffffu, acc[j], 10);
        float t2 = __shfl_down_sync(0xffffffffu, acc[j], 20);
        acc[j] += t1 + t2;
    }

    if (grp == 0) {
        float di = g_dis[node];
        float4 b = ((const float4*)b2)[li];
        float4 r;
        r.x = fmaf(di, acc[0], b.x);
        r.y = fmaf(di, acc[1], b.y);
        r.z = fmaf(di, acc[2], b.z);
        r.w = fmaf(di, acc[3], b.w);
        ((float4*)out)[(size_t)node * 10 + li] = r;
    }
}

// ---------------- launch ----------------
extern "C" void kernel_launch(void* const* d_in, const int* in_sizes, int n_in,
                              void* d_out, int out_size) {
    const float* x    = (const float*)d_in[0];
    const void*  eidx = d_in[1];
    const float* W1   = (const float*)d_in[2];
    const float* b1   = (const float*)d_in[3];
    const float* W2   = (const float*)d_in[4];
    const float* b2   = (const float*)d_in[5];
    float* out = (float*)d_out;

    static cudaStream_t s2 = nullptr;
    static cudaEvent_t evD = nullptr, evG = nullptr;
    static bool use2 = false;
    if (!s2) {
        use2 = (cudaStreamCreateWithFlags(&s2, cudaStreamNonBlocking) == cudaSuccess) &&
               (cudaEventCreateWithFlags(&evD, cudaEventDisableTiming) == cudaSuccess) &&
               (cudaEventCreateWithFlags(&evG, cudaEventDisableTiming) == cudaSuccess);
        if (!use2) s2 = (cudaStream_t)0x1;
    }

    k_init<<<(NN + 255) / 256, 256>>>((const int*)eidx);
    k_count<<<(EE / 8 + 255) / 256, 256>>>(eidx);
    k_scan<<<NB_SCAN, SCAN_B>>>();                      // dis ready here

    if (use2) {
        cudaEventRecord(evD, 0);
        cudaStreamWaitEvent(s2, evD, 0);
        k_gemm1<<<(NN + 127) / 128, 128, 0, s2>>>(x, W1);  // ∥ fill
        cudaEventRecord(evG, s2);

        k_fill<<<(EE / 8 + 255) / 256, 256>>>(eidx);

        cudaStreamWaitEvent(0, evG, 0);
    } else {
        k_gemm1<<<(NN + 127) / 128, 128>>>(x, W1);
        k_fill<<<(EE / 8 + 255) / 256, 256>>>(eidx);
    }

    k_agg1<<<NN / 8, 256>>>(b1);
    k_gemm2<<<(NN + 255) / 256, 128>>>(W2);
    k_agg2<<<NN / 8, 256>>>(b2, out);
}